// round 15
// baseline (speedup 1.0000x reference)
#include <cuda_runtime.h>
#include <cuda_fp16.h>
#include <math.h>
#include <cstdint>

#define SEQ   2048
#define BATCH 2
#define DMODEL 1024
#define NH    16
#define DH    64
#define HALF  32
#define BHN   (BATCH*NH)        // 32
#define MTOK  (BATCH*SEQ)       // 4096

typedef unsigned long long u64;
typedef __half f16;

// -------- scratch (device globals; no allocation allowed) --------
__device__ f16 g_x16[(size_t)MTOK * DMODEL];
__device__ f16 g_ao16[(size_t)MTOK * DMODEL];
__device__ f16 g_wq[(size_t)3 * DMODEL * DMODEL];   // [3072][1024] transposed
__device__ f16 g_wp[(size_t)DMODEL * DMODEL];       // [1024][1024] transposed

// roped q/k and v, single fp16, layout (bh, s, d)
__device__ f16 g_q16[(size_t)BHN * SEQ * DH];
__device__ f16 g_k16[(size_t)BHN * SEQ * DH];
__device__ f16 g_v16[(size_t)BHN * SEQ * DH];

// ---------------- helpers ----------------
__device__ __forceinline__ uint32_t smem_u32(const void* p) {
    uint32_t a; asm("{ .reg .u64 t; cvta.to.shared.u64 t, %1; cvt.u32.u64 %0, t; }"
                    : "=r"(a) : "l"(p));
    return a;
}
__device__ __forceinline__ void ldsm_x4(uint32_t* r, uint32_t addr) {
    asm volatile("ldmatrix.sync.aligned.m8n8.x4.shared.b16 {%0,%1,%2,%3}, [%4];"
                 : "=r"(r[0]), "=r"(r[1]), "=r"(r[2]), "=r"(r[3]) : "r"(addr));
}
__device__ __forceinline__ void ldsm_x4_t(uint32_t* r, uint32_t addr) {
    asm volatile("ldmatrix.sync.aligned.m8n8.x4.trans.shared.b16 {%0,%1,%2,%3}, [%4];"
                 : "=r"(r[0]), "=r"(r[1]), "=r"(r[2]), "=r"(r[3]) : "r"(addr));
}
__device__ __forceinline__ void mma_f16(float* c, const uint32_t* a,
                                        uint32_t b0, uint32_t b1) {
    asm volatile("mma.sync.aligned.m16n8k16.row.col.f32.f16.f16.f32 "
                 "{%0,%1,%2,%3}, {%4,%5,%6,%7}, {%8,%9}, {%0,%1,%2,%3};"
                 : "+f"(c[0]), "+f"(c[1]), "+f"(c[2]), "+f"(c[3])
                 : "r"(a[0]), "r"(a[1]), "r"(a[2]), "r"(a[3]), "r"(b0), "r"(b1));
}
__device__ __forceinline__ void cpa16(uint32_t smem, const void* g) {
    asm volatile("cp.async.cg.shared.global [%0], [%1], 16;" :: "r"(smem), "l"(g));
}
#define CPA_COMMIT() asm volatile("cp.async.commit_group;" ::: "memory")
#define CPA_WAIT(n)  asm volatile("cp.async.wait_group %0;" :: "n"(n) : "memory")

__device__ __forceinline__ uint32_t f2h2(float lo, float hi) {
    half2 t = __floats2half2_rn(lo, hi);
    return *(uint32_t*)&t;
}

// 128B-row swizzled tiles (64 fp16 per row)
__device__ __forceinline__ uint32_t tile_off(int row, int segByte) {
    return (uint32_t)(row * 128 + (segByte ^ ((row & 7) * 16)));
}
__device__ __forceinline__ uint32_t frag_addr(uint32_t tbase, int rowbase, int ks, int lane) {
    int r = rowbase + (lane & 15);
    return tbase + tile_off(r, ks * 32 + (lane >> 4) * 16);
}

// ============ fused prep: x -> fp16 AND both weight transposes =================
__global__ __launch_bounds__(256) void prep(const float* __restrict__ x,
                                            const float* __restrict__ wq_in,
                                            const float* __restrict__ wp_in)
{
    int bid = blockIdx.x;
    if (bid < 4096) {
        int idx = bid * 256 + threadIdx.x;           // float4 id
        float4 v = *(const float4*)(x + (size_t)idx * 4);
        uint32_t p0 = f2h2(v.x, v.y), p1 = f2h2(v.z, v.w);
        *(uint2*)(g_x16 + (size_t)idx * 4) = make_uint2(p0, p1);
        return;
    }
    __shared__ float t[32][33];
    int wid2 = bid - 4096;                           // 0..4095
    int bx = wid2 & 127, by = wid2 >> 7;             // bx 0..127, by 0..31
    const float* in; f16* o; int N;
    if (bx < 96) { in = wq_in; o = g_wq; N = 3 * DMODEL; }
    else         { in = wp_in; o = g_wp; N = DMODEL; bx -= 96; }
    int n0 = bx * 32, k0 = by * 32;
    int tx = threadIdx.x & 31, ty = threadIdx.x >> 5;
#pragma unroll
    for (int r = 0; r < 4; r++)
        t[ty + 8 * r][tx] = in[(size_t)(k0 + ty + 8 * r) * N + n0 + tx];
    __syncthreads();
#pragma unroll
    for (int r = 0; r < 4; r++)
        o[(size_t)(n0 + ty + 8 * r) * DMODEL + k0 + tx] = __float2half_rn(t[tx][ty + 8 * r]);
}

// ====== fp16 GEMM: C = A x B^T, 128x128 tile, BK=64, 3-stage, 1 sync/iter =======
#define GEMM_SMEM (98304)

__global__ __launch_bounds__(256, 1) void gemm_mma(const f16* __restrict__ A,
                                                   const f16* __restrict__ B,
                                                   float* __restrict__ C,
                                                   const float* __restrict__ rc,
                                                   const float* __restrict__ rs,
                                                   int N, int K, int fuse_rope)
{
    extern __shared__ char dsm[];
    uint32_t sbase = smem_u32(dsm);

    int tid = threadIdx.x;
    int w = tid >> 5, lane = tid & 31;
    int wm = w & 3, wn = w >> 2;      // warp tile: rows wm*32, cols wn*64
    int bx = blockIdx.x, by = blockIdx.y;

    const f16* A_b = A + (size_t)(by * 128) * K;
    const f16* B_b = B + (size_t)(bx * 128) * K;

    float acc[2][8][4];
#pragma unroll
    for (int mi = 0; mi < 2; mi++)
#pragma unroll
        for (int ni = 0; ni < 8; ni++)
#pragma unroll
            for (int q = 0; q < 4; q++) acc[mi][ni][q] = 0.f;

    int m_ld = tid >> 3, seg = tid & 7;          // 32 rows x 8 segs per pass
    uint32_t so0 = tile_off(m_ld, seg * 16);

    auto load_chunk = [&](int kc, int st) {
        uint32_t sb_st = sbase + (uint32_t)st * 32768u;
#pragma unroll
        for (int l = 0; l < 4; l++) {
            int m = m_ld + l * 32;
            uint32_t so = so0 + (uint32_t)(l * 32 * 128);
            cpa16(sb_st + so,         A_b + (size_t)m * K + kc + seg * 8);
            cpa16(sb_st + 16384 + so, B_b + (size_t)m * K + kc + seg * 8);
        }
        CPA_COMMIT();
    };

    int nchunk = K >> 6;                         // 16
    load_chunk(0, 0);
    if (nchunk > 1) load_chunk(64, 1);

    int st = 0;
    for (int ck = 0; ck < nchunk; ck++) {
        if (ck + 1 < nchunk) { CPA_WAIT(1); } else { CPA_WAIT(0); }
        __syncthreads();

        uint32_t sb_st = sbase + (uint32_t)st * 32768u;
        uint32_t tA = sb_st, tB = sb_st + 16384;

#pragma unroll
        for (int ks = 0; ks < 4; ks++) {
            uint32_t af[2][4];
#pragma unroll
            for (int mi = 0; mi < 2; mi++)
                ldsm_x4(af[mi], frag_addr(tA, wm * 32 + mi * 16, ks, lane));
            uint32_t bf[4][4];
#pragma unroll
            for (int n4 = 0; n4 < 4; n4++)
                ldsm_x4(bf[n4], frag_addr(tB, wn * 64 + n4 * 16, ks, lane));
#pragma unroll
            for (int mi = 0; mi < 2; mi++)
#pragma unroll
                for (int n4 = 0; n4 < 4; n4++) {
                    mma_f16(acc[mi][n4 * 2],     af[mi], bf[n4][0], bf[n4][2]);
                    mma_f16(acc[mi][n4 * 2 + 1], af[mi], bf[n4][1], bf[n4][3]);
                }
        }

        if (ck + 2 < nchunk) {
            int st2 = st + 2; if (st2 >= 3) st2 -= 3;
            load_chunk((ck + 2) << 6, st2);
        }
        if (++st == 3) st = 0;
    }

    int g = lane >> 2, t4 = lane & 3;
    if (!fuse_rope) {
#pragma unroll
        for (int mi = 0; mi < 2; mi++)
#pragma unroll
            for (int ni = 0; ni < 8; ni++) {
                int row = by * 128 + wm * 32 + mi * 16 + g;
                int col = bx * 128 + wn * 64 + ni * 8 + t4 * 2;
                *(float2*)(C + (size_t)row * N + col) = make_float2(acc[mi][ni][0], acc[mi][ni][1]);
                *(float2*)(C + (size_t)(row + 8) * N + col) = make_float2(acc[mi][ni][2], acc[mi][ni][3]);
            }
    } else {
        int colbase = bx * 128 + wn * 64;
        int sec = colbase >> 10;              // 0=q 1=k 2=v (same for warp)
        int cc0 = colbase & 1023;
        int h = cc0 >> 6;                     // head (same for warp)
        f16* O = (sec == 0) ? g_q16 : (sec == 1) ? g_k16 : g_v16;
#pragma unroll
        for (int mi = 0; mi < 2; mi++)
#pragma unroll
            for (int ni = 0; ni < 8; ni++) {
                int d = ((cc0 + ni * 8) & 63) + t4 * 2;     // even
                int row0 = by * 128 + wm * 32 + mi * 16 + g;
#pragma unroll
                for (int rr = 0; rr < 2; rr++) {
                    int row = row0 + rr * 8;
                    float a0 = acc[mi][ni][rr * 2], a1 = acc[mi][ni][rr * 2 + 1];
                    int b = row >> 11, s = row & (SEQ - 1);
                    float x0, x1;
                    if (sec == 2) { x0 = a0; x1 = a1; }
                    else {
                        float c = rc[s * DH + d], sn = rs[s * DH + d];
                        x0 = a0 * c - a1 * sn;
                        x1 = a1 * c + a0 * sn;
                    }
                    size_t dst = ((size_t)(b * NH + h) * SEQ + s) * DH + d;
                    *(uint32_t*)(O + dst) = f2h2(x0, x1);
                }
            }
    }
}

// === flash fp16: packed h2exp2 softmax, 3-stage K/V pipeline, 2 CTA/SM ==========
#define FL_SMEM (65536)

__global__ __launch_bounds__(256, 2) void flash_mma()
{
    extern __shared__ char fsm[];
    uint32_t sb = smem_u32(fsm);
    uint32_t QT = sb;                     // Q tile 16KB; stages at +16KB*(1+st)

    int tid = threadIdx.x;
    int w = tid >> 5, lane = tid & 31;
    int g = lane >> 2, t4 = lane & 3;
    int it = blockIdx.x, bh = blockIdx.y;
    int i0 = it * 128;
    int b = bh >> 4, h = bh & (NH - 1);

    const f16* Qg = g_q16 + ((size_t)bh * SEQ + i0) * DH;
    const f16* Kg = g_k16 + (size_t)bh * SEQ * DH;
    const f16* Vg = g_v16 + (size_t)bh * SEQ * DH;

    int row_ld = tid >> 3, seg = tid & 7;
    auto load_kv = [&](int j0, int st) {
        uint32_t base = sb + 16384u + (uint32_t)st * 16384u;
#pragma unroll
        for (int l = 0; l < 2; l++) {
            int r = row_ld + l * 32;
            uint32_t so = tile_off(r, seg * 16);
            cpa16(base + so,        Kg + (size_t)(j0 + r) * DH + seg * 8);
            cpa16(base + 8192 + so, Vg + (size_t)(j0 + r) * DH + seg * 8);
        }
        CPA_COMMIT();
    };

    // Q + first K/V committed together; stage 1 prefetch
#pragma unroll
    for (int l = 0; l < 4; l++) {
        int r = row_ld + l * 32;
        uint32_t so = tile_off(r, seg * 16);
        cpa16(QT + so, Qg + (size_t)r * DH + seg * 8);
    }
    load_kv(0, 0);
    load_kv(64, 1);

    float o[8][4];
#pragma unroll
    for (int n = 0; n < 8; n++)
#pragma unroll
        for (int q = 0; q < 4; q++) o[n][q] = 0.f;
    float psum0 = 0.f, psum1 = 0.f;

    const float scale2 = 0.25503526f;     // 32^-0.5 * log2(e)
    const int njt = SEQ / 64;

    int st = 0;
    for (int jt = 0; jt < njt; jt++) {
        int j0 = jt * 64;
        if (jt + 1 < njt) { CPA_WAIT(1); } else { CPA_WAIT(0); }
        __syncthreads();

        uint32_t KB = sb + 16384u + (uint32_t)st * 16384u;
        uint32_t KT = KB, VT = KB + 8192;

        float sac[8][4];
        int mode = (jt <= 2 * it - 1) ? 1 : ((jt >= 2 * it + 2) ? 0 : 2);

        if (mode < 2) {
#pragma unroll
            for (int n = 0; n < 8; n++)
#pragma unroll
                for (int q = 0; q < 4; q++) sac[n][q] = 0.f;
            int ksb = mode ? 2 : 0;   // dn half = dims 32..63
#pragma unroll
            for (int k2 = 0; k2 < 2; k2++) {
                int ks = ksb + k2;
                uint32_t qf[4];
                ldsm_x4(qf, frag_addr(QT, w * 16, ks, lane));
                uint32_t kf[4][4];
#pragma unroll
                for (int n4 = 0; n4 < 4; n4++)
                    ldsm_x4(kf[n4], frag_addr(KT, n4 * 16, ks, lane));
#pragma unroll
                for (int n4 = 0; n4 < 4; n4++) {
                    mma_f16(sac[n4 * 2],     qf, kf[n4][0], kf[n4][2]);
                    mma_f16(sac[n4 * 2 + 1], qf, kf[n4][1], kf[n4][3]);
                }
            }
        } else {
            // diagonal tile: per-n4 both halves
#pragma unroll
            for (int n4 = 0; n4 < 4; n4++) {
                float su[2][4], sd[2][4];
#pragma unroll
                for (int hh = 0; hh < 2; hh++)
#pragma unroll
                    for (int q = 0; q < 4; q++) { su[hh][q] = 0.f; sd[hh][q] = 0.f; }
#pragma unroll
                for (int ks = 0; ks < 4; ks++) {
                    uint32_t qf[4], kf[4];
                    ldsm_x4(qf, frag_addr(QT, w * 16, ks, lane));
                    ldsm_x4(kf, frag_addr(KT, n4 * 16, ks, lane));
                    float (*tg)[4] = (ks < 2) ? su : sd;   // up = dims 0..31
                    mma_f16(tg[0], qf, kf[0], kf[2]);
                    mma_f16(tg[1], qf, kf[1], kf[3]);
                }
#pragma unroll
                for (int hh = 0; hh < 2; hh++)
#pragma unroll
                    for (int q = 0; q < 4; q++) {
                        int i = i0 + w * 16 + g + ((q >= 2) ? 8 : 0);
                        int j = j0 + (n4 * 2 + hh) * 8 + 2 * t4 + (q & 1);
                        sac[n4 * 2 + hh][q] = (j <= i) ? sd[hh][q] : su[hh][q];
                    }
            }
        }

        // ---- packed softmax: 2^(s*scale2) via h2exp2; results ARE the A-frags --
        uint32_t e01[8], e23[8];
#pragma unroll
        for (int n = 0; n < 8; n++) {
            uint32_t p01 = f2h2(sac[n][0] * scale2, sac[n][1] * scale2);
            uint32_t p23 = f2h2(sac[n][2] * scale2, sac[n][3] * scale2);
            half2 r01 = h2exp2(*(half2*)&p01);
            half2 r23 = h2exp2(*(half2*)&p23);
            e01[n] = *(uint32_t*)&r01;
            e23[n] = *(uint32_t*)&r23;
            float2 f01 = __half22float2(r01), f23 = __half22float2(r23);
            psum0 += f01.x + f01.y;
            psum1 += f23.x + f23.y;
        }

        // ---- PV ----
#pragma unroll
        for (int kt = 0; kt < 4; kt++) {
            uint32_t pa[4] = {e01[2 * kt], e23[2 * kt], e01[2 * kt + 1], e23[2 * kt + 1]};
            uint32_t vf[4][4];
#pragma unroll
            for (int n4 = 0; n4 < 4; n4++)
                ldsm_x4_t(vf[n4], frag_addr(VT, kt * 16, n4, lane));
#pragma unroll
            for (int n4 = 0; n4 < 4; n4++) {
                mma_f16(o[n4 * 2],     pa, vf[n4][0], vf[n4][1]);
                mma_f16(o[n4 * 2 + 1], pa, vf[n4][2], vf[n4][3]);
            }
        }

        if (jt + 2 < njt) {
            int st2 = st + 2; if (st2 >= 3) st2 -= 3;
            load_kv((jt + 2) * 64, st2);
        }
        if (++st == 3) st = 0;
    }

    // ---- end-only row-sum reduction ----
    psum0 += __shfl_xor_sync(0xffffffffu, psum0, 1);
    psum0 += __shfl_xor_sync(0xffffffffu, psum0, 2);
    psum1 += __shfl_xor_sync(0xffffffffu, psum1, 1);
    psum1 += __shfl_xor_sync(0xffffffffu, psum1, 2);
    float inv0 = 1.f / psum0, inv1 = 1.f / psum1;

    int i_g0 = i0 + w * 16 + g;
#pragma unroll
    for (int n = 0; n < 8; n++) {
        int col = h * DH + n * 8 + 2 * t4;
        size_t r0 = (size_t)(b * SEQ + i_g0) * DMODEL + col;
        size_t r1 = (size_t)(b * SEQ + i_g0 + 8) * DMODEL + col;
        *(uint32_t*)(g_ao16 + r0) = f2h2(o[n][0] * inv0, o[n][1] * inv0);
        *(uint32_t*)(g_ao16 + r1) = f2h2(o[n][2] * inv1, o[n][3] * inv1);
    }
}

// =================================================================================
extern "C" void kernel_launch(void* const* d_in, const int* in_sizes, int n_in,
                              void* d_out, int out_size)
{
    const float* x      = (const float*)d_in[0];
    const float* w_qkv  = (const float*)d_in[1];
    const float* w_proj = (const float*)d_in[2];
    const float* rc     = (const float*)d_in[3];
    const float* rs     = (const float*)d_in[4];
    float* out = (float*)d_out;

    f16 *x16, *ao16, *wq, *wp;
    cudaGetSymbolAddress((void**)&x16,  g_x16);
    cudaGetSymbolAddress((void**)&ao16, g_ao16);
    cudaGetSymbolAddress((void**)&wq,   g_wq);
    cudaGetSymbolAddress((void**)&wp,   g_wp);

    cudaFuncSetAttribute(gemm_mma,  cudaFuncAttributeMaxDynamicSharedMemorySize, GEMM_SMEM);
    cudaFuncSetAttribute(flash_mma, cudaFuncAttributeMaxDynamicSharedMemorySize, FL_SMEM);

    // 0) fused prep: x conversion + both weight transposes
    prep<<<8192, 256>>>(x, w_qkv, w_proj);

    // 1) QKV GEMM + fused RoPE epilogue
    gemm_mma<<<dim3(3 * DMODEL / 128, MTOK / 128), 256, GEMM_SMEM>>>(
        x16, wq, nullptr, rc, rs, 3 * DMODEL, DMODEL, 1);
    // 2) flash attention (writes ao16 directly)
    flash_mma<<<dim3(SEQ / 128, BHN), 256, FL_SMEM>>>();
    // 3) proj GEMM
    gemm_mma<<<dim3(DMODEL / 128, MTOK / 128), 256, GEMM_SMEM>>>(
        ao16, wp, out, nullptr, nullptr, DMODEL, DMODEL, 0);
}

// round 16
// speedup vs baseline: 1.0074x; 1.0074x over previous
#include <cuda_runtime.h>
#include <cuda_fp16.h>
#include <math.h>
#include <cstdint>

#define SEQ   2048
#define BATCH 2
#define DMODEL 1024
#define NH    16
#define DH    64
#define HALF  32
#define BHN   (BATCH*NH)        // 32
#define MTOK  (BATCH*SEQ)       // 4096

typedef unsigned long long u64;
typedef __half f16;

// -------- scratch (device globals; no allocation allowed) --------
__device__ f16 g_x16[(size_t)MTOK * DMODEL];
__device__ f16 g_ao16[(size_t)MTOK * DMODEL];
__device__ f16 g_wq[(size_t)3 * DMODEL * DMODEL];   // [3072][1024] transposed
__device__ f16 g_wp[(size_t)DMODEL * DMODEL];       // [1024][1024] transposed

// roped q/k and v, single fp16, layout (bh, s, d)
__device__ f16 g_q16[(size_t)BHN * SEQ * DH];
__device__ f16 g_k16[(size_t)BHN * SEQ * DH];
__device__ f16 g_v16[(size_t)BHN * SEQ * DH];

// ---------------- helpers ----------------
__device__ __forceinline__ uint32_t smem_u32(const void* p) {
    uint32_t a; asm("{ .reg .u64 t; cvta.to.shared.u64 t, %1; cvt.u32.u64 %0, t; }"
                    : "=r"(a) : "l"(p));
    return a;
}
__device__ __forceinline__ void ldsm_x4(uint32_t* r, uint32_t addr) {
    asm volatile("ldmatrix.sync.aligned.m8n8.x4.shared.b16 {%0,%1,%2,%3}, [%4];"
                 : "=r"(r[0]), "=r"(r[1]), "=r"(r[2]), "=r"(r[3]) : "r"(addr));
}
__device__ __forceinline__ void ldsm_x4_t(uint32_t* r, uint32_t addr) {
    asm volatile("ldmatrix.sync.aligned.m8n8.x4.trans.shared.b16 {%0,%1,%2,%3}, [%4];"
                 : "=r"(r[0]), "=r"(r[1]), "=r"(r[2]), "=r"(r[3]) : "r"(addr));
}
__device__ __forceinline__ void mma_f16(float* c, const uint32_t* a,
                                        uint32_t b0, uint32_t b1) {
    asm volatile("mma.sync.aligned.m16n8k16.row.col.f32.f16.f16.f32 "
                 "{%0,%1,%2,%3}, {%4,%5,%6,%7}, {%8,%9}, {%0,%1,%2,%3};"
                 : "+f"(c[0]), "+f"(c[1]), "+f"(c[2]), "+f"(c[3])
                 : "r"(a[0]), "r"(a[1]), "r"(a[2]), "r"(a[3]), "r"(b0), "r"(b1));
}
__device__ __forceinline__ void cpa16(uint32_t smem, const void* g) {
    asm volatile("cp.async.cg.shared.global [%0], [%1], 16;" :: "r"(smem), "l"(g));
}
#define CPA_COMMIT() asm volatile("cp.async.commit_group;" ::: "memory")
#define CPA_WAIT(n)  asm volatile("cp.async.wait_group %0;" :: "n"(n) : "memory")

__device__ __forceinline__ uint32_t f2h2(float lo, float hi) {
    half2 t = __floats2half2_rn(lo, hi);
    return *(uint32_t*)&t;
}

// 128B-row swizzled tiles (64 fp16 per row)
__device__ __forceinline__ uint32_t tile_off(int row, int segByte) {
    return (uint32_t)(row * 128 + (segByte ^ ((row & 7) * 16)));
}
__device__ __forceinline__ uint32_t frag_addr(uint32_t tbase, int rowbase, int ks, int lane) {
    int r = rowbase + (lane & 15);
    return tbase + tile_off(r, ks * 32 + (lane >> 4) * 16);
}

// ============ fused prep: x -> fp16 AND both weight transposes =================
__global__ __launch_bounds__(256) void prep(const float* __restrict__ x,
                                            const float* __restrict__ wq_in,
                                            const float* __restrict__ wp_in)
{
    int bid = blockIdx.x;
    if (bid < 4096) {
        int idx = bid * 256 + threadIdx.x;           // float4 id
        float4 v = *(const float4*)(x + (size_t)idx * 4);
        uint32_t p0 = f2h2(v.x, v.y), p1 = f2h2(v.z, v.w);
        *(uint2*)(g_x16 + (size_t)idx * 4) = make_uint2(p0, p1);
        return;
    }
    __shared__ float t[32][33];
    int wid2 = bid - 4096;                           // 0..4095
    int bx = wid2 & 127, by = wid2 >> 7;             // bx 0..127, by 0..31
    const float* in; f16* o; int N;
    if (bx < 96) { in = wq_in; o = g_wq; N = 3 * DMODEL; }
    else         { in = wp_in; o = g_wp; N = DMODEL; bx -= 96; }
    int n0 = bx * 32, k0 = by * 32;
    int tx = threadIdx.x & 31, ty = threadIdx.x >> 5;
#pragma unroll
    for (int r = 0; r < 4; r++)
        t[ty + 8 * r][tx] = in[(size_t)(k0 + ty + 8 * r) * N + n0 + tx];
    __syncthreads();
#pragma unroll
    for (int r = 0; r < 4; r++)
        o[(size_t)(n0 + ty + 8 * r) * DMODEL + k0 + tx] = __float2half_rn(t[tx][ty + 8 * r]);
}

// ====== fp16 GEMM: 128x128 tile, BK=64, 3-stage, early prefetch, 1 sync/iter ====
#define GEMM_SMEM (98304)

__global__ __launch_bounds__(256, 1) void gemm_mma(const f16* __restrict__ A,
                                                   const f16* __restrict__ B,
                                                   float* __restrict__ C,
                                                   const float* __restrict__ rc,
                                                   const float* __restrict__ rs,
                                                   int N, int K, int fuse_rope)
{
    extern __shared__ char dsm[];
    uint32_t sbase = smem_u32(dsm);

    int tid = threadIdx.x;
    int w = tid >> 5, lane = tid & 31;
    int wm = w & 3, wn = w >> 2;      // warp tile: rows wm*32, cols wn*64
    int bx = blockIdx.x, by = blockIdx.y;

    const f16* A_b = A + (size_t)(by * 128) * K;
    const f16* B_b = B + (size_t)(bx * 128) * K;

    float acc[2][8][4];
#pragma unroll
    for (int mi = 0; mi < 2; mi++)
#pragma unroll
        for (int ni = 0; ni < 8; ni++)
#pragma unroll
            for (int q = 0; q < 4; q++) acc[mi][ni][q] = 0.f;

    int m_ld = tid >> 3, seg = tid & 7;          // 32 rows x 8 segs per pass
    uint32_t so0 = tile_off(m_ld, seg * 16);

    auto load_chunk = [&](int kc, int st) {
        uint32_t sb_st = sbase + (uint32_t)st * 32768u;
#pragma unroll
        for (int l = 0; l < 4; l++) {
            int m = m_ld + l * 32;
            uint32_t so = so0 + (uint32_t)(l * 32 * 128);
            cpa16(sb_st + so,         A_b + (size_t)m * K + kc + seg * 8);
            cpa16(sb_st + 16384 + so, B_b + (size_t)m * K + kc + seg * 8);
        }
        CPA_COMMIT();
    };

    int nchunk = K >> 6;                         // 16
    load_chunk(0, 0);
    if (nchunk > 1) load_chunk(64, 1);

    int st = 0;
    for (int ck = 0; ck < nchunk; ck++) {
        if (ck + 1 < nchunk) { CPA_WAIT(1); } else { CPA_WAIT(0); }
        __syncthreads();

        // early prefetch: issue stage +2 before compute so it hides under mma
        if (ck + 2 < nchunk) {
            int st2 = st + 2; if (st2 >= 3) st2 -= 3;
            load_chunk((ck + 2) << 6, st2);
        }

        uint32_t sb_st = sbase + (uint32_t)st * 32768u;
        uint32_t tA = sb_st, tB = sb_st + 16384;

#pragma unroll
        for (int ks = 0; ks < 4; ks++) {
            uint32_t af[2][4];
#pragma unroll
            for (int mi = 0; mi < 2; mi++)
                ldsm_x4(af[mi], frag_addr(tA, wm * 32 + mi * 16, ks, lane));
            uint32_t bf[4][4];
#pragma unroll
            for (int n4 = 0; n4 < 4; n4++)
                ldsm_x4(bf[n4], frag_addr(tB, wn * 64 + n4 * 16, ks, lane));
#pragma unroll
            for (int mi = 0; mi < 2; mi++)
#pragma unroll
                for (int n4 = 0; n4 < 4; n4++) {
                    mma_f16(acc[mi][n4 * 2],     af[mi], bf[n4][0], bf[n4][2]);
                    mma_f16(acc[mi][n4 * 2 + 1], af[mi], bf[n4][1], bf[n4][3]);
                }
        }
        if (++st == 3) st = 0;
    }

    int g = lane >> 2, t4 = lane & 3;
    if (!fuse_rope) {
#pragma unroll
        for (int mi = 0; mi < 2; mi++)
#pragma unroll
            for (int ni = 0; ni < 8; ni++) {
                int row = by * 128 + wm * 32 + mi * 16 + g;
                int col = bx * 128 + wn * 64 + ni * 8 + t4 * 2;
                *(float2*)(C + (size_t)row * N + col) = make_float2(acc[mi][ni][0], acc[mi][ni][1]);
                *(float2*)(C + (size_t)(row + 8) * N + col) = make_float2(acc[mi][ni][2], acc[mi][ni][3]);
            }
    } else {
        int colbase = bx * 128 + wn * 64;
        int sec = colbase >> 10;              // 0=q 1=k 2=v (same for warp)
        int cc0 = colbase & 1023;
        int h = cc0 >> 6;                     // head (same for warp)
        f16* O = (sec == 0) ? g_q16 : (sec == 1) ? g_k16 : g_v16;
#pragma unroll
        for (int mi = 0; mi < 2; mi++)
#pragma unroll
            for (int ni = 0; ni < 8; ni++) {
                int d = ((cc0 + ni * 8) & 63) + t4 * 2;     // even
                int row0 = by * 128 + wm * 32 + mi * 16 + g;
#pragma unroll
                for (int rr = 0; rr < 2; rr++) {
                    int row = row0 + rr * 8;
                    float a0 = acc[mi][ni][rr * 2], a1 = acc[mi][ni][rr * 2 + 1];
                    int b = row >> 11, s = row & (SEQ - 1);
                    float x0, x1;
                    if (sec == 2) { x0 = a0; x1 = a1; }
                    else {
                        float c = rc[s * DH + d], sn = rs[s * DH + d];
                        x0 = a0 * c - a1 * sn;
                        x1 = a1 * c + a0 * sn;
                    }
                    size_t dst = ((size_t)(b * NH + h) * SEQ + s) * DH + d;
                    *(uint32_t*)(O + dst) = f2h2(x0, x1);
                }
            }
    }
}

// === flash fp16: fixed-max expf softmax, 3-stage pipeline, early prefetch =======
#define FL_SMEM (65536)

__global__ __launch_bounds__(256, 2) void flash_mma()
{
    extern __shared__ char fsm[];
    uint32_t sb = smem_u32(fsm);
    uint32_t QT = sb;                     // Q tile 16KB; stages at +16KB*(1+st)

    int tid = threadIdx.x;
    int w = tid >> 5, lane = tid & 31;
    int g = lane >> 2, t4 = lane & 3;
    int it = blockIdx.x, bh = blockIdx.y;
    int i0 = it * 128;
    int b = bh >> 4, h = bh & (NH - 1);

    const f16* Qg = g_q16 + ((size_t)bh * SEQ + i0) * DH;
    const f16* Kg = g_k16 + (size_t)bh * SEQ * DH;
    const f16* Vg = g_v16 + (size_t)bh * SEQ * DH;

    int row_ld = tid >> 3, seg = tid & 7;
    auto load_kv = [&](int j0, int st) {
        uint32_t base = sb + 16384u + (uint32_t)st * 16384u;
#pragma unroll
        for (int l = 0; l < 2; l++) {
            int r = row_ld + l * 32;
            uint32_t so = tile_off(r, seg * 16);
            cpa16(base + so,        Kg + (size_t)(j0 + r) * DH + seg * 8);
            cpa16(base + 8192 + so, Vg + (size_t)(j0 + r) * DH + seg * 8);
        }
        CPA_COMMIT();
    };

    // Q + first K/V committed together; stage 1 prefetch
#pragma unroll
    for (int l = 0; l < 4; l++) {
        int r = row_ld + l * 32;
        uint32_t so = tile_off(r, seg * 16);
        cpa16(QT + so, Qg + (size_t)r * DH + seg * 8);
    }
    load_kv(0, 0);
    load_kv(64, 1);

    float o[8][4];
#pragma unroll
    for (int n = 0; n < 8; n++)
#pragma unroll
        for (int q = 0; q < 4; q++) o[n][q] = 0.f;
    float psum0 = 0.f, psum1 = 0.f;

    const float scale = 0.17677669529663687f;
    const int njt = SEQ / 64;

    int st = 0;
    for (int jt = 0; jt < njt; jt++) {
        int j0 = jt * 64;
        if (jt + 1 < njt) { CPA_WAIT(1); } else { CPA_WAIT(0); }
        __syncthreads();

        // early prefetch: issue stage +2 before compute
        if (jt + 2 < njt) {
            int st2 = st + 2; if (st2 >= 3) st2 -= 3;
            load_kv((jt + 2) * 64, st2);
        }

        uint32_t KB = sb + 16384u + (uint32_t)st * 16384u;
        uint32_t KT = KB, VT = KB + 8192;

        float sac[8][4];
        int mode = (jt <= 2 * it - 1) ? 1 : ((jt >= 2 * it + 2) ? 0 : 2);

        if (mode < 2) {
#pragma unroll
            for (int n = 0; n < 8; n++)
#pragma unroll
                for (int q = 0; q < 4; q++) sac[n][q] = 0.f;
            int ksb = mode ? 2 : 0;   // dn half = dims 32..63
#pragma unroll
            for (int k2 = 0; k2 < 2; k2++) {
                int ks = ksb + k2;
                uint32_t qf[4];
                ldsm_x4(qf, frag_addr(QT, w * 16, ks, lane));
                uint32_t kf[4][4];
#pragma unroll
                for (int n4 = 0; n4 < 4; n4++)
                    ldsm_x4(kf[n4], frag_addr(KT, n4 * 16, ks, lane));
#pragma unroll
                for (int n4 = 0; n4 < 4; n4++) {
                    mma_f16(sac[n4 * 2],     qf, kf[n4][0], kf[n4][2]);
                    mma_f16(sac[n4 * 2 + 1], qf, kf[n4][1], kf[n4][3]);
                }
            }
        } else {
            // diagonal tile: per-n4 both halves
#pragma unroll
            for (int n4 = 0; n4 < 4; n4++) {
                float su[2][4], sd[2][4];
#pragma unroll
                for (int hh = 0; hh < 2; hh++)
#pragma unroll
                    for (int q = 0; q < 4; q++) { su[hh][q] = 0.f; sd[hh][q] = 0.f; }
#pragma unroll
                for (int ks = 0; ks < 4; ks++) {
                    uint32_t qf[4], kf[4];
                    ldsm_x4(qf, frag_addr(QT, w * 16, ks, lane));
                    ldsm_x4(kf, frag_addr(KT, n4 * 16, ks, lane));
                    float (*tg)[4] = (ks < 2) ? su : sd;   // up = dims 0..31
                    mma_f16(tg[0], qf, kf[0], kf[2]);
                    mma_f16(tg[1], qf, kf[1], kf[3]);
                }
#pragma unroll
                for (int hh = 0; hh < 2; hh++)
#pragma unroll
                    for (int q = 0; q < 4; q++) {
                        int i = i0 + w * 16 + g + ((q >= 2) ? 8 : 0);
                        int j = j0 + (n4 * 2 + hh) * 8 + 2 * t4 + (q & 1);
                        sac[n4 * 2 + hh][q] = (j <= i) ? sd[hh][q] : su[hh][q];
                    }
            }
        }

        // ---- fixed-max softmax ----
#pragma unroll
        for (int n = 0; n < 8; n++) {
            sac[n][0] = __expf(sac[n][0] * scale);
            sac[n][1] = __expf(sac[n][1] * scale);
            sac[n][2] = __expf(sac[n][2] * scale);
            sac[n][3] = __expf(sac[n][3] * scale);
            psum0 += sac[n][0] + sac[n][1];
            psum1 += sac[n][2] + sac[n][3];
        }

        // ---- PV ----
#pragma unroll
        for (int kt = 0; kt < 4; kt++) {
            uint32_t pa[4];
#pragma unroll
            for (int hh = 0; hh < 2; hh++) {
                pa[hh * 2 + 0] = f2h2(sac[2 * kt + hh][0], sac[2 * kt + hh][1]);
                pa[hh * 2 + 1] = f2h2(sac[2 * kt + hh][2], sac[2 * kt + hh][3]);
            }
            uint32_t vf[4][4];
#pragma unroll
            for (int n4 = 0; n4 < 4; n4++)
                ldsm_x4_t(vf[n4], frag_addr(VT, kt * 16, n4, lane));
#pragma unroll
            for (int n4 = 0; n4 < 4; n4++) {
                mma_f16(o[n4 * 2],     pa, vf[n4][0], vf[n4][1]);
                mma_f16(o[n4 * 2 + 1], pa, vf[n4][2], vf[n4][3]);
            }
        }
        if (++st == 3) st = 0;
    }

    // ---- end-only row-sum reduction ----
    psum0 += __shfl_xor_sync(0xffffffffu, psum0, 1);
    psum0 += __shfl_xor_sync(0xffffffffu, psum0, 2);
    psum1 += __shfl_xor_sync(0xffffffffu, psum1, 1);
    psum1 += __shfl_xor_sync(0xffffffffu, psum1, 2);
    float inv0 = 1.f / psum0, inv1 = 1.f / psum1;

    int i_g0 = i0 + w * 16 + g;
#pragma unroll
    for (int n = 0; n < 8; n++) {
        int col = h * DH + n * 8 + 2 * t4;
        size_t r0 = (size_t)(b * SEQ + i_g0) * DMODEL + col;
        size_t r1 = (size_t)(b * SEQ + i_g0 + 8) * DMODEL + col;
        *(uint32_t*)(g_ao16 + r0) = f2h2(o[n][0] * inv0, o[n][1] * inv0);
        *(uint32_t*)(g_ao16 + r1) = f2h2(o[n][2] * inv1, o[n][3] * inv1);
    }
}

// =================================================================================
extern "C" void kernel_launch(void* const* d_in, const int* in_sizes, int n_in,
                              void* d_out, int out_size)
{
    const float* x      = (const float*)d_in[0];
    const float* w_qkv  = (const float*)d_in[1];
    const float* w_proj = (const float*)d_in[2];
    const float* rc     = (const float*)d_in[3];
    const float* rs     = (const float*)d_in[4];
    float* out = (float*)d_out;

    f16 *x16, *ao16, *wq, *wp;
    cudaGetSymbolAddress((void**)&x16,  g_x16);
    cudaGetSymbolAddress((void**)&ao16, g_ao16);
    cudaGetSymbolAddress((void**)&wq,   g_wq);
    cudaGetSymbolAddress((void**)&wp,   g_wp);

    cudaFuncSetAttribute(gemm_mma,  cudaFuncAttributeMaxDynamicSharedMemorySize, GEMM_SMEM);
    cudaFuncSetAttribute(flash_mma, cudaFuncAttributeMaxDynamicSharedMemorySize, FL_SMEM);

    // 0) fused prep: x conversion + both weight transposes
    prep<<<8192, 256>>>(x, w_qkv, w_proj);

    // 1) QKV GEMM + fused RoPE epilogue
    gemm_mma<<<dim3(3 * DMODEL / 128, MTOK / 128), 256, GEMM_SMEM>>>(
        x16, wq, nullptr, rc, rs, 3 * DMODEL, DMODEL, 1);
    // 2) flash attention (writes ao16 directly)
    flash_mma<<<dim3(SEQ / 128, BHN), 256, FL_SMEM>>>();
    // 3) proj GEMM
    gemm_mma<<<dim3(DMODEL / 128, MTOK / 128), 256, GEMM_SMEM>>>(
        ao16, wp, out, nullptr, nullptr, DMODEL, DMODEL, 0);
}

// round 17
// speedup vs baseline: 1.1355x; 1.1272x over previous
#include <cuda_runtime.h>
#include <cuda_fp16.h>
#include <math.h>
#include <cstdint>

#define SEQ   2048
#define BATCH 2
#define DMODEL 1024
#define NH    16
#define DH    64
#define HALF  32
#define BHN   (BATCH*NH)        // 32
#define MTOK  (BATCH*SEQ)       // 4096

typedef unsigned long long u64;
typedef __half f16;

// -------- scratch (device globals; no allocation allowed) --------
__device__ f16 g_x16[(size_t)MTOK * DMODEL];
__device__ f16 g_ao16[(size_t)MTOK * DMODEL];
__device__ f16 g_wq[(size_t)3 * DMODEL * DMODEL];   // [3072][1024] transposed
__device__ f16 g_wp[(size_t)DMODEL * DMODEL];       // [1024][1024] transposed

// roped q/k and v, single fp16, layout (bh, s, d)
__device__ f16 g_q16[(size_t)BHN * SEQ * DH];
__device__ f16 g_k16[(size_t)BHN * SEQ * DH];
__device__ f16 g_v16[(size_t)BHN * SEQ * DH];

// ---------------- helpers ----------------
__device__ __forceinline__ uint32_t smem_u32(const void* p) {
    uint32_t a; asm("{ .reg .u64 t; cvta.to.shared.u64 t, %1; cvt.u32.u64 %0, t; }"
                    : "=r"(a) : "l"(p));
    return a;
}
__device__ __forceinline__ void ldsm_x4(uint32_t* r, uint32_t addr) {
    asm volatile("ldmatrix.sync.aligned.m8n8.x4.shared.b16 {%0,%1,%2,%3}, [%4];"
                 : "=r"(r[0]), "=r"(r[1]), "=r"(r[2]), "=r"(r[3]) : "r"(addr));
}
__device__ __forceinline__ void ldsm_x4_t(uint32_t* r, uint32_t addr) {
    asm volatile("ldmatrix.sync.aligned.m8n8.x4.trans.shared.b16 {%0,%1,%2,%3}, [%4];"
                 : "=r"(r[0]), "=r"(r[1]), "=r"(r[2]), "=r"(r[3]) : "r"(addr));
}
__device__ __forceinline__ void mma_f16(float* c, const uint32_t* a,
                                        uint32_t b0, uint32_t b1) {
    asm volatile("mma.sync.aligned.m16n8k16.row.col.f32.f16.f16.f32 "
                 "{%0,%1,%2,%3}, {%4,%5,%6,%7}, {%8,%9}, {%0,%1,%2,%3};"
                 : "+f"(c[0]), "+f"(c[1]), "+f"(c[2]), "+f"(c[3])
                 : "r"(a[0]), "r"(a[1]), "r"(a[2]), "r"(a[3]), "r"(b0), "r"(b1));
}
__device__ __forceinline__ void cpa16(uint32_t smem, const void* g) {
    asm volatile("cp.async.cg.shared.global [%0], [%1], 16;" :: "r"(smem), "l"(g));
}
#define CPA_COMMIT() asm volatile("cp.async.commit_group;" ::: "memory")
#define CPA_WAIT(n)  asm volatile("cp.async.wait_group %0;" :: "n"(n) : "memory")

__device__ __forceinline__ uint32_t f2h2(float lo, float hi) {
    half2 t = __floats2half2_rn(lo, hi);
    return *(uint32_t*)&t;
}

// 128B-row swizzled tiles (64 fp16 per row)
__device__ __forceinline__ uint32_t tile_off(int row, int segByte) {
    return (uint32_t)(row * 128 + (segByte ^ ((row & 7) * 16)));
}
__device__ __forceinline__ uint32_t frag_addr(uint32_t tbase, int rowbase, int ks, int lane) {
    int r = rowbase + (lane & 15);
    return tbase + tile_off(r, ks * 32 + (lane >> 4) * 16);
}

// ============ fused prep: x -> fp16 AND both weight transposes =================
__global__ __launch_bounds__(256) void prep(const float* __restrict__ x,
                                            const float* __restrict__ wq_in,
                                            const float* __restrict__ wp_in)
{
    int bid = blockIdx.x;
    if (bid < 4096) {
        int idx = bid * 256 + threadIdx.x;           // float4 id
        float4 v = *(const float4*)(x + (size_t)idx * 4);
        uint32_t p0 = f2h2(v.x, v.y), p1 = f2h2(v.z, v.w);
        *(uint2*)(g_x16 + (size_t)idx * 4) = make_uint2(p0, p1);
        return;
    }
    __shared__ float t[32][33];
    int wid2 = bid - 4096;                           // 0..4095
    int bx = wid2 & 127, by = wid2 >> 7;             // bx 0..127, by 0..31
    const float* in; f16* o; int N;
    if (bx < 96) { in = wq_in; o = g_wq; N = 3 * DMODEL; }
    else         { in = wp_in; o = g_wp; N = DMODEL; bx -= 96; }
    int n0 = bx * 32, k0 = by * 32;
    int tx = threadIdx.x & 31, ty = threadIdx.x >> 5;
#pragma unroll
    for (int r = 0; r < 4; r++)
        t[ty + 8 * r][tx] = in[(size_t)(k0 + ty + 8 * r) * N + n0 + tx];
    __syncthreads();
#pragma unroll
    for (int r = 0; r < 4; r++)
        o[(size_t)(n0 + ty + 8 * r) * DMODEL + k0 + tx] = __float2half_rn(t[tx][ty + 8 * r]);
}

// ====== fp16 GEMM: 64x128 tile, BK=64, 3-stage, late prefetch, 2 CTA/SM =========
#define GEMM_SMEM (73728)

__global__ __launch_bounds__(256, 2) void gemm_mma(const f16* __restrict__ A,
                                                   const f16* __restrict__ B,
                                                   float* __restrict__ C,
                                                   const float* __restrict__ rc,
                                                   const float* __restrict__ rs,
                                                   int N, int K, int fuse_rope)
{
    extern __shared__ char dsm[];
    uint32_t sbase = smem_u32(dsm);

    int tid = threadIdx.x;
    int w = tid >> 5, lane = tid & 31;
    int wm = w & 1, wn = w >> 1;      // warp tile: rows wm*32, cols wn*32
    int bx = blockIdx.x, by = blockIdx.y;

    const f16* A_b = A + (size_t)(by * 64) * K;
    const f16* B_b = B + (size_t)(bx * 128) * K;

    float acc[2][4][4];
#pragma unroll
    for (int mi = 0; mi < 2; mi++)
#pragma unroll
        for (int ni = 0; ni < 4; ni++)
#pragma unroll
            for (int q = 0; q < 4; q++) acc[mi][ni][q] = 0.f;

    int m_ld = tid >> 3, seg = tid & 7;          // 32 rows x 8 segs per pass
    auto load_chunk = [&](int kc, int st) {
        uint32_t sb_st = sbase + (uint32_t)st * 24576u;
        // A: 64 rows (2 passes)
#pragma unroll
        for (int l = 0; l < 2; l++) {
            int m = m_ld + l * 32;
            cpa16(sb_st + tile_off(m, seg * 16), A_b + (size_t)m * K + kc + seg * 8);
        }
        // B: 128 rows (4 passes) at +8KB
#pragma unroll
        for (int l = 0; l < 4; l++) {
            int m = m_ld + l * 32;
            cpa16(sb_st + 8192 + tile_off(m, seg * 16), B_b + (size_t)m * K + kc + seg * 8);
        }
        CPA_COMMIT();
    };

    int nchunk = K >> 6;                         // 16
    load_chunk(0, 0);
    load_chunk(64, 1);

    int st = 0;
    for (int ck = 0; ck < nchunk; ck++) {
        if (ck + 1 < nchunk) { CPA_WAIT(1); } else { CPA_WAIT(0); }
        __syncthreads();

        uint32_t sb_st = sbase + (uint32_t)st * 24576u;
        uint32_t tA = sb_st, tB = sb_st + 8192;

#pragma unroll
        for (int ks = 0; ks < 4; ks++) {
            uint32_t af[2][4];
#pragma unroll
            for (int mi = 0; mi < 2; mi++)
                ldsm_x4(af[mi], frag_addr(tA, wm * 32 + mi * 16, ks, lane));
            uint32_t bf[2][4];
#pragma unroll
            for (int n4 = 0; n4 < 2; n4++)
                ldsm_x4(bf[n4], frag_addr(tB, wn * 32 + n4 * 16, ks, lane));
#pragma unroll
            for (int mi = 0; mi < 2; mi++)
#pragma unroll
                for (int n4 = 0; n4 < 2; n4++) {
                    mma_f16(acc[mi][n4 * 2],     af[mi], bf[n4][0], bf[n4][2]);
                    mma_f16(acc[mi][n4 * 2 + 1], af[mi], bf[n4][1], bf[n4][3]);
                }
        }

        if (ck + 2 < nchunk) {
            int st2 = st + 2; if (st2 >= 3) st2 -= 3;
            load_chunk((ck + 2) << 6, st2);
        }
        if (++st == 3) st = 0;
    }

    int g = lane >> 2, t4 = lane & 3;
    if (!fuse_rope) {
#pragma unroll
        for (int mi = 0; mi < 2; mi++)
#pragma unroll
            for (int ni = 0; ni < 4; ni++) {
                int row = by * 64 + wm * 32 + mi * 16 + g;
                int col = bx * 128 + wn * 32 + ni * 8 + t4 * 2;
                *(float2*)(C + (size_t)row * N + col) = make_float2(acc[mi][ni][0], acc[mi][ni][1]);
                *(float2*)(C + (size_t)(row + 8) * N + col) = make_float2(acc[mi][ni][2], acc[mi][ni][3]);
            }
    } else {
        int colbase = bx * 128 + wn * 32;
        int sec = colbase >> 10;              // 0=q 1=k 2=v (same for warp)
        int cc0 = colbase & 1023;
        int h = cc0 >> 6;                     // head (same for warp: 32-col span)
        f16* O = (sec == 0) ? g_q16 : (sec == 1) ? g_k16 : g_v16;
#pragma unroll
        for (int mi = 0; mi < 2; mi++)
#pragma unroll
            for (int ni = 0; ni < 4; ni++) {
                int d = ((cc0 + ni * 8) & 63) + t4 * 2;     // even
                int row0 = by * 64 + wm * 32 + mi * 16 + g;
#pragma unroll
                for (int rr = 0; rr < 2; rr++) {
                    int row = row0 + rr * 8;
                    float a0 = acc[mi][ni][rr * 2], a1 = acc[mi][ni][rr * 2 + 1];
                    int b = row >> 11, s = row & (SEQ - 1);
                    float x0, x1;
                    if (sec == 2) { x0 = a0; x1 = a1; }
                    else {
                        float c = rc[s * DH + d], sn = rs[s * DH + d];
                        x0 = a0 * c - a1 * sn;
                        x1 = a1 * c + a0 * sn;
                    }
                    size_t dst = ((size_t)(b * NH + h) * SEQ + s) * DH + d;
                    *(uint32_t*)(O + dst) = f2h2(x0, x1);
                }
            }
    }
}

// === flash fp16: 64-row i-tiles, 128 threads, 4 CTA/SM, 3-stage pipeline ========
#define FL_SMEM (57344)

__global__ __launch_bounds__(128, 4) void flash_mma()
{
    extern __shared__ char fsm[];
    uint32_t sb = smem_u32(fsm);
    uint32_t QT = sb;                     // Q tile 8KB; stages at +8KB + st*16KB

    int tid = threadIdx.x;
    int w = tid >> 5, lane = tid & 31;    // w 0..3
    int g = lane >> 2, t4 = lane & 3;
    int it = blockIdx.x, bh = blockIdx.y;
    int i0 = it * 64;
    int b = bh >> 4, h = bh & (NH - 1);

    const f16* Qg = g_q16 + ((size_t)bh * SEQ + i0) * DH;
    const f16* Kg = g_k16 + (size_t)bh * SEQ * DH;
    const f16* Vg = g_v16 + (size_t)bh * SEQ * DH;

    int row_ld = tid >> 3, seg = tid & 7; // 16 rows x 8 segs per pass
    auto load_kv = [&](int j0, int st) {
        uint32_t base = sb + 8192u + (uint32_t)st * 16384u;
#pragma unroll
        for (int l = 0; l < 4; l++) {
            int r = row_ld + l * 16;
            uint32_t so = tile_off(r, seg * 16);
            cpa16(base + so,        Kg + (size_t)(j0 + r) * DH + seg * 8);
            cpa16(base + 8192 + so, Vg + (size_t)(j0 + r) * DH + seg * 8);
        }
        CPA_COMMIT();
    };

    // Q (64 rows) + first K/V; stage 1 prefetch
#pragma unroll
    for (int l = 0; l < 4; l++) {
        int r = row_ld + l * 16;
        cpa16(QT + tile_off(r, seg * 16), Qg + (size_t)r * DH + seg * 8);
    }
    load_kv(0, 0);
    load_kv(64, 1);

    float o[8][4];
#pragma unroll
    for (int n = 0; n < 8; n++)
#pragma unroll
        for (int q = 0; q < 4; q++) o[n][q] = 0.f;
    float psum0 = 0.f, psum1 = 0.f;

    const float scale = 0.17677669529663687f;
    const int njt = SEQ / 64;

    int st = 0;
    for (int jt = 0; jt < njt; jt++) {
        int j0 = jt * 64;
        if (jt + 1 < njt) { CPA_WAIT(1); } else { CPA_WAIT(0); }
        __syncthreads();

        uint32_t KB = sb + 8192u + (uint32_t)st * 16384u;
        uint32_t KT = KB, VT = KB + 8192;

        float sac[8][4];
        int mode = (jt < it) ? 1 : ((jt > it) ? 0 : 2);

        if (mode < 2) {
#pragma unroll
            for (int n = 0; n < 8; n++)
#pragma unroll
                for (int q = 0; q < 4; q++) sac[n][q] = 0.f;
            int ksb = mode ? 2 : 0;   // dn half = dims 32..63
#pragma unroll
            for (int k2 = 0; k2 < 2; k2++) {
                int ks = ksb + k2;
                uint32_t qf[4];
                ldsm_x4(qf, frag_addr(QT, w * 16, ks, lane));
                uint32_t kf[4][4];
#pragma unroll
                for (int n4 = 0; n4 < 4; n4++)
                    ldsm_x4(kf[n4], frag_addr(KT, n4 * 16, ks, lane));
#pragma unroll
                for (int n4 = 0; n4 < 4; n4++) {
                    mma_f16(sac[n4 * 2],     qf, kf[n4][0], kf[n4][2]);
                    mma_f16(sac[n4 * 2 + 1], qf, kf[n4][1], kf[n4][3]);
                }
            }
        } else {
            // single diagonal tile: per-n4 both halves
#pragma unroll
            for (int n4 = 0; n4 < 4; n4++) {
                float su[2][4], sd[2][4];
#pragma unroll
                for (int hh = 0; hh < 2; hh++)
#pragma unroll
                    for (int q = 0; q < 4; q++) { su[hh][q] = 0.f; sd[hh][q] = 0.f; }
#pragma unroll
                for (int ks = 0; ks < 4; ks++) {
                    uint32_t qf[4], kf[4];
                    ldsm_x4(qf, frag_addr(QT, w * 16, ks, lane));
                    ldsm_x4(kf, frag_addr(KT, n4 * 16, ks, lane));
                    float (*tg)[4] = (ks < 2) ? su : sd;   // up = dims 0..31
                    mma_f16(tg[0], qf, kf[0], kf[2]);
                    mma_f16(tg[1], qf, kf[1], kf[3]);
                }
#pragma unroll
                for (int hh = 0; hh < 2; hh++)
#pragma unroll
                    for (int q = 0; q < 4; q++) {
                        int i = i0 + w * 16 + g + ((q >= 2) ? 8 : 0);
                        int j = j0 + (n4 * 2 + hh) * 8 + 2 * t4 + (q & 1);
                        sac[n4 * 2 + hh][q] = (j <= i) ? sd[hh][q] : su[hh][q];
                    }
            }
        }

        // ---- fixed-max softmax ----
#pragma unroll
        for (int n = 0; n < 8; n++) {
            sac[n][0] = __expf(sac[n][0] * scale);
            sac[n][1] = __expf(sac[n][1] * scale);
            sac[n][2] = __expf(sac[n][2] * scale);
            sac[n][3] = __expf(sac[n][3] * scale);
            psum0 += sac[n][0] + sac[n][1];
            psum1 += sac[n][2] + sac[n][3];
        }

        // ---- PV ----
#pragma unroll
        for (int kt = 0; kt < 4; kt++) {
            uint32_t pa[4];
#pragma unroll
            for (int hh = 0; hh < 2; hh++) {
                pa[hh * 2 + 0] = f2h2(sac[2 * kt + hh][0], sac[2 * kt + hh][1]);
                pa[hh * 2 + 1] = f2h2(sac[2 * kt + hh][2], sac[2 * kt + hh][3]);
            }
            uint32_t vf[4][4];
#pragma unroll
            for (int n4 = 0; n4 < 4; n4++)
                ldsm_x4_t(vf[n4], frag_addr(VT, kt * 16, n4, lane));
#pragma unroll
            for (int n4 = 0; n4 < 4; n4++) {
                mma_f16(o[n4 * 2],     pa, vf[n4][0], vf[n4][1]);
                mma_f16(o[n4 * 2 + 1], pa, vf[n4][2], vf[n4][3]);
            }
        }

        if (jt + 2 < njt) {
            int st2 = st + 2; if (st2 >= 3) st2 -= 3;
            load_kv((jt + 2) * 64, st2);
        }
        if (++st == 3) st = 0;
    }

    // ---- end-only row-sum reduction ----
    psum0 += __shfl_xor_sync(0xffffffffu, psum0, 1);
    psum0 += __shfl_xor_sync(0xffffffffu, psum0, 2);
    psum1 += __shfl_xor_sync(0xffffffffu, psum1, 1);
    psum1 += __shfl_xor_sync(0xffffffffu, psum1, 2);
    float inv0 = 1.f / psum0, inv1 = 1.f / psum1;

    int i_g0 = i0 + w * 16 + g;
#pragma unroll
    for (int n = 0; n < 8; n++) {
        int col = h * DH + n * 8 + 2 * t4;
        size_t r0 = (size_t)(b * SEQ + i_g0) * DMODEL + col;
        size_t r1 = (size_t)(b * SEQ + i_g0 + 8) * DMODEL + col;
        *(uint32_t*)(g_ao16 + r0) = f2h2(o[n][0] * inv0, o[n][1] * inv0);
        *(uint32_t*)(g_ao16 + r1) = f2h2(o[n][2] * inv1, o[n][3] * inv1);
    }
}

// =================================================================================
extern "C" void kernel_launch(void* const* d_in, const int* in_sizes, int n_in,
                              void* d_out, int out_size)
{
    const float* x      = (const float*)d_in[0];
    const float* w_qkv  = (const float*)d_in[1];
    const float* w_proj = (const float*)d_in[2];
    const float* rc     = (const float*)d_in[3];
    const float* rs     = (const float*)d_in[4];
    float* out = (float*)d_out;

    f16 *x16, *ao16, *wq, *wp;
    cudaGetSymbolAddress((void**)&x16,  g_x16);
    cudaGetSymbolAddress((void**)&ao16, g_ao16);
    cudaGetSymbolAddress((void**)&wq,   g_wq);
    cudaGetSymbolAddress((void**)&wp,   g_wp);

    cudaFuncSetAttribute(gemm_mma,  cudaFuncAttributeMaxDynamicSharedMemorySize, GEMM_SMEM);
    cudaFuncSetAttribute(flash_mma, cudaFuncAttributeMaxDynamicSharedMemorySize, FL_SMEM);

    // 0) fused prep: x conversion + both weight transposes
    prep<<<8192, 256>>>(x, w_qkv, w_proj);

    // 1) QKV GEMM + fused RoPE epilogue (64-row tiles: 24 x 64 grid)
    gemm_mma<<<dim3(3 * DMODEL / 128, MTOK / 64), 256, GEMM_SMEM>>>(
        x16, wq, nullptr, rc, rs, 3 * DMODEL, DMODEL, 1);
    // 2) flash attention (64-row i-tiles)
    flash_mma<<<dim3(SEQ / 64, BHN), 128, FL_SMEM>>>();
    // 3) proj GEMM
    gemm_mma<<<dim3(DMODEL / 128, MTOK / 64), 256, GEMM_SMEM>>>(
        ao16, wp, out, nullptr, nullptr, DMODEL, DMODEL, 0);
}